// round 1
// baseline (speedup 1.0000x reference)
#include <cuda_runtime.h>
#include <math.h>

// Problem constants
#define Bn   2
#define Cc   256
#define Hh   56
#define Ww   56
#define Ll   3136        // 56*56
#define CrD  64          // reduced channels
#define Gg   16          // groups
#define KKt  49          // 7*7
#define M2   784         // K*K*G
#define OUT_OFF (Bn*Cc*Ll)   // 1605632: kernel output starts here

// Scratch (no cudaMalloc allowed)
__device__ float g_t[Bn*CrD*Ll];   // conv1 output, pre-BN
__device__ float g_scale[CrD];
__device__ float g_shift[CrD];

// ---------------------------------------------------------------------------
// Tiled GEMM: C[b][m][n] = sum_k W[m][k] * f(A[b][k][n]) + bias[m]
// N per batch = 3136 (multiple of 64). BM=BN=64, BK=16, 256 threads, 4x4 micro.
// FUSE: apply BN(scale,shift)+ReLU to A elements while loading.
// ---------------------------------------------------------------------------
template<bool FUSE>
__global__ void gemm_kernel(const float* __restrict__ W,
                            const float* __restrict__ A,
                            const float* __restrict__ bias,
                            float* __restrict__ Cmat,
                            int M, int Kd)
{
    const int N = Ll;
    __shared__ float Ws[16][64];
    __shared__ float As[16][64];

    int b   = blockIdx.z;
    int bm0 = blockIdx.y * 64;
    int bn0 = blockIdx.x * 64;
    int tid = threadIdx.x;
    int tx  = tid & 15;      // 0..15 -> N
    int ty  = tid >> 4;      // 0..15 -> M

    float acc[4][4];
#pragma unroll
    for (int i = 0; i < 4; i++)
#pragma unroll
        for (int j = 0; j < 4; j++) acc[i][j] = 0.f;

    const float* Ab = A + (size_t)b * Kd * N;

    for (int k0 = 0; k0 < Kd; k0 += 16) {
        // load W tile 64(m) x 16(k)
#pragma unroll
        for (int i = 0; i < 4; i++) {
            int idx = tid + i * 256;
            int m  = idx & 63;
            int kk = idx >> 6;
            int gm = bm0 + m;
            Ws[kk][m] = (gm < M) ? W[(size_t)gm * Kd + k0 + kk] : 0.f;
        }
        // load A tile 16(k) x 64(n)
#pragma unroll
        for (int i = 0; i < 4; i++) {
            int idx = tid + i * 256;
            int n  = idx & 63;
            int kk = idx >> 6;
            float v = Ab[(size_t)(k0 + kk) * N + bn0 + n];
            if (FUSE)
                v = fmaxf(fmaf(v, g_scale[k0 + kk], g_shift[k0 + kk]), 0.f);
            As[kk][n] = v;
        }
        __syncthreads();
#pragma unroll
        for (int kk = 0; kk < 16; kk++) {
            float wr[4], ar[4];
#pragma unroll
            for (int i = 0; i < 4; i++) wr[i] = Ws[kk][ty * 4 + i];
#pragma unroll
            for (int j = 0; j < 4; j++) ar[j] = As[kk][tx * 4 + j];
#pragma unroll
            for (int i = 0; i < 4; i++)
#pragma unroll
                for (int j = 0; j < 4; j++)
                    acc[i][j] = fmaf(wr[i], ar[j], acc[i][j]);
        }
        __syncthreads();
    }

#pragma unroll
    for (int i = 0; i < 4; i++) {
        int gm = bm0 + ty * 4 + i;
        if (gm < M) {
            float bb = bias[gm];
#pragma unroll
            for (int j = 0; j < 4; j++)
                Cmat[(size_t)b * M * N + (size_t)gm * N + bn0 + tx * 4 + j] =
                    acc[i][j] + bb;
        }
    }
}

// ---------------------------------------------------------------------------
// BN stats over (B, H, W) per channel of g_t; fold gamma/beta into scale/shift.
// ---------------------------------------------------------------------------
__global__ void bn_stats_kernel(const float* __restrict__ gamma,
                                const float* __restrict__ beta)
{
    int ch  = blockIdx.x;
    int tid = threadIdx.x;
    double ds = 0.0, ds2 = 0.0;
    for (int i = tid; i < Bn * Ll; i += 256) {
        int b = i / Ll;
        int l = i - b * Ll;
        float v = g_t[((size_t)b * CrD + ch) * Ll + l];
        ds  += v;
        ds2 += (double)v * v;
    }
    __shared__ double sh[256], sh2[256];
    sh[tid] = ds; sh2[tid] = ds2;
    __syncthreads();
    for (int o = 128; o > 0; o >>= 1) {
        if (tid < o) { sh[tid] += sh[tid + o]; sh2[tid] += sh2[tid + o]; }
        __syncthreads();
    }
    if (tid == 0) {
        double n    = (double)(Bn * Ll);
        double mean = sh[0] / n;
        double var  = sh2[0] / n - mean * mean;
        float rstd  = rsqrtf((float)var + 1e-5f);
        float sc    = gamma[ch] * rstd;
        g_scale[ch] = sc;
        g_shift[ch] = beta[ch] - (float)mean * sc;
    }
}

// ---------------------------------------------------------------------------
// Involution contraction.
// Output flat (per batch): F = cg*50176 + q*3136 + l  ->  channel cg*16+q, sp l
// out[F] = sum_kk kgen[b, kk*16+q, l] * x[b, 16*cg + t/49, yp+di, xp+dj]
//   where t = kk*16+q, kkp = t%49, di = kkp/7-3, dj = kkp%7-3.
// One thread: fixed (b,q,l), 16 cg accumulators share the 49 kernel values.
// ---------------------------------------------------------------------------
__global__ void involution_kernel(const float* __restrict__ x,
                                  const float* __restrict__ kgen,
                                  float* __restrict__ out)
{
    int l = blockIdx.x * 256 + threadIdx.x;
    if (l >= Ll) return;
    int q = blockIdx.y;
    int b = blockIdx.z;
    int yp = l / Ww;
    int xp = l - yp * Ww;

    float acc[16];
#pragma unroll
    for (int i = 0; i < 16; i++) acc[i] = 0.f;

    const float* kb = kgen + (size_t)b * M2 * Ll;
    const float* xb = x    + (size_t)b * Cc * Ll;

#pragma unroll 7
    for (int kk = 0; kk < KKt; kk++) {
        int t  = kk * Gg + q;
        float kv = kb[(size_t)t * Ll + l];
        int dc  = t / KKt;
        int kkp = t - dc * KKt;
        int di  = kkp / 7 - 3;
        int dj  = kkp - (kkp / 7) * 7 - 3;
        int yy = yp + di;
        int xx = xp + dj;
        if ((unsigned)yy < Hh && (unsigned)xx < Ww) {
            const float* xpt = xb + (size_t)dc * Ll + yy * Ww + xx;
#pragma unroll
            for (int cg = 0; cg < 16; cg++)
                acc[cg] = fmaf(kv, xpt[(size_t)cg * (Gg * Ll)], acc[cg]);
        }
    }

#pragma unroll
    for (int cg = 0; cg < 16; cg++)
        out[(size_t)b * Cc * Ll + (size_t)(cg * Gg + q) * Ll + l] = acc[cg];
}

// ---------------------------------------------------------------------------
extern "C" void kernel_launch(void* const* d_in, const int* in_sizes, int n_in,
                              void* d_out, int out_size)
{
    const float* x     = (const float*)d_in[0];
    const float* w1    = (const float*)d_in[1];
    const float* b1    = (const float*)d_in[2];
    const float* gamma = (const float*)d_in[3];
    const float* beta  = (const float*)d_in[4];
    const float* w2    = (const float*)d_in[5];
    const float* b2    = (const float*)d_in[6];

    float* out  = (float*)d_out;
    float* kgen = out + OUT_OFF;     // kernel output region

    float* t_ptr = nullptr;
    cudaGetSymbolAddress((void**)&t_ptr, g_t);

    // 1) conv1: t = w1 @ x + b1   (M=64, K=256, N=3136, batched z=2)
    {
        dim3 grid(Ll / 64, 1, Bn);
        gemm_kernel<false><<<grid, 256>>>(w1, x, b1, t_ptr, CrD, Cc);
    }
    // 2) BN batch stats -> scale/shift
    bn_stats_kernel<<<CrD, 256>>>(gamma, beta);

    // 3) conv2 with fused BN+ReLU on input: k = w2 @ relu(bn(t)) + b2
    //    written directly into d_out kernel region (raw-view equivalence)
    {
        dim3 grid(Ll / 64, (M2 + 63) / 64, Bn);
        gemm_kernel<true><<<grid, 256>>>(w2, t_ptr, b2, kgen, M2, CrD);
    }
    // 4) involution contraction -> main output
    {
        dim3 grid((Ll + 255) / 256, Gg, Bn);
        involution_kernel<<<grid, 256>>>(x, kgen, out);
    }
}

// round 3
// speedup vs baseline: 1.8794x; 1.8794x over previous
#include <cuda_runtime.h>
#include <math.h>

#define Bn   2
#define Cc   256
#define Hh   56
#define Ww   56
#define Ll   3136
#define CrD  64
#define Gg   16
#define KKt  49
#define M2   784
#define OUT_OFF (Bn*Cc*Ll)

__device__ float g_t[Bn*CrD*Ll];
__device__ float g_scale[CrD];
__device__ float g_shift[CrD];

// ---------------------------------------------------------------------------
// Tiled GEMM: C[b][m][n] = sum_k W[m][k] * f(A[b][k][n]) + bias[m]
// 256 threads. Block tile: (16*TM) x 64, BK=16. Micro-tile TM x 4.
// Vectorized float4 smem loads. N = 3136 (divisible by 64). M guarded.
// ---------------------------------------------------------------------------
template<int TM, bool FUSE>
__global__ void gemm_kernel(const float* __restrict__ W,
                            const float* __restrict__ A,
                            const float* __restrict__ bias,
                            float* __restrict__ Cmat,
                            int M, int Kd)
{
    const int N  = Ll;
    const int BM = 16 * TM;
    __shared__ float Ws[16][16 * TM];
    __shared__ float As[16][64];

    int b   = blockIdx.z;
    int bm0 = blockIdx.y * BM;
    int bn0 = blockIdx.x * 64;
    int tid = threadIdx.x;
    int tx  = tid & 15;
    int ty  = tid >> 4;

    float acc[TM][4];
#pragma unroll
    for (int i = 0; i < TM; i++)
#pragma unroll
        for (int j = 0; j < 4; j++) acc[i][j] = 0.f;

    const float* Ab = A + (size_t)b * Kd * N;

    for (int k0 = 0; k0 < Kd; k0 += 16) {
        // W tile: BM x 16  (float4 along k).  BM*4 float4 loads total.
#pragma unroll
        for (int i = 0; i < TM / 4; i++) {
            int idx = tid + i * 256;       // 0 .. BM*4-1
            int m   = idx >> 2;
            int k4  = idx & 3;
            int gm  = bm0 + m;
            float4 v = make_float4(0.f, 0.f, 0.f, 0.f);
            if (gm < M)
                v = *(const float4*)&W[(size_t)gm * Kd + k0 + k4 * 4];
            Ws[k4 * 4 + 0][m] = v.x;
            Ws[k4 * 4 + 1][m] = v.y;
            Ws[k4 * 4 + 2][m] = v.z;
            Ws[k4 * 4 + 3][m] = v.w;
        }
        // A tile: 16 x 64 (float4 along n)
        {
            int kk = tid >> 4;
            int n4 = tid & 15;
            float4 v = *(const float4*)&Ab[(size_t)(k0 + kk) * N + bn0 + n4 * 4];
            if (FUSE) {
                float sc = g_scale[k0 + kk], sh = g_shift[k0 + kk];
                v.x = fmaxf(fmaf(v.x, sc, sh), 0.f);
                v.y = fmaxf(fmaf(v.y, sc, sh), 0.f);
                v.z = fmaxf(fmaf(v.z, sc, sh), 0.f);
                v.w = fmaxf(fmaf(v.w, sc, sh), 0.f);
            }
            *(float4*)&As[kk][n4 * 4] = v;
        }
        __syncthreads();
#pragma unroll
        for (int kk = 0; kk < 16; kk++) {
            float4 a4 = *(const float4*)&As[kk][tx * 4];
            float wr[TM];
#pragma unroll
            for (int j = 0; j < TM / 4; j++) {
                float4 w4 = *(const float4*)&Ws[kk][ty * TM + j * 4];
                wr[j * 4 + 0] = w4.x; wr[j * 4 + 1] = w4.y;
                wr[j * 4 + 2] = w4.z; wr[j * 4 + 3] = w4.w;
            }
#pragma unroll
            for (int i = 0; i < TM; i++) {
                acc[i][0] = fmaf(wr[i], a4.x, acc[i][0]);
                acc[i][1] = fmaf(wr[i], a4.y, acc[i][1]);
                acc[i][2] = fmaf(wr[i], a4.z, acc[i][2]);
                acc[i][3] = fmaf(wr[i], a4.w, acc[i][3]);
            }
        }
        __syncthreads();
    }

#pragma unroll
    for (int i = 0; i < TM; i++) {
        int gm = bm0 + ty * TM + i;
        if (gm < M) {
            float bb = bias[gm];
            float4 v = make_float4(acc[i][0] + bb, acc[i][1] + bb,
                                   acc[i][2] + bb, acc[i][3] + bb);
            *(float4*)&Cmat[(size_t)b * M * N + (size_t)gm * N + bn0 + tx * 4] = v;
        }
    }
}

// ---------------------------------------------------------------------------
__global__ void bn_stats_kernel(const float* __restrict__ gamma,
                                const float* __restrict__ beta)
{
    int ch  = blockIdx.x;
    int tid = threadIdx.x;
    double ds = 0.0, ds2 = 0.0;
    for (int i = tid; i < Bn * Ll; i += 256) {
        int b = i / Ll;
        int l = i - b * Ll;
        float v = g_t[((size_t)b * CrD + ch) * Ll + l];
        ds  += v;
        ds2 += (double)v * v;
    }
    __shared__ double sh[256], sh2[256];
    sh[tid] = ds; sh2[tid] = ds2;
    __syncthreads();
    for (int o = 128; o > 0; o >>= 1) {
        if (tid < o) { sh[tid] += sh[tid + o]; sh2[tid] += sh2[tid + o]; }
        __syncthreads();
    }
    if (tid == 0) {
        double n    = (double)(Bn * Ll);
        double mean = sh[0] / n;
        double var  = sh2[0] / n - mean * mean;
        float rstd  = rsqrtf((float)var + 1e-5f);
        float sc    = gamma[ch] * rstd;
        g_scale[ch] = sc;
        g_shift[ch] = beta[ch] - (float)mean * sc;
    }
}

// ---------------------------------------------------------------------------
// Involution contraction, cg-split by 2 (8 cg per thread).
// Key identity: x index = xb + dc*Ll + l + di*56 + dj = xb + off(kk) + l,
// off precomputed in smem. Interior pixels (yp,xp in [3,52]) skip all bounds
// checks -> branch-free 8-LDG/8-FFMA bursts.
// grid: (13, 16 q, 4 = b*2+half), 256 threads over l.
// ---------------------------------------------------------------------------
__global__ void involution_kernel(const float* __restrict__ x,
                                  const float* __restrict__ kgen,
                                  float* __restrict__ out)
{
    __shared__ int s_off[64];
    __shared__ int s_di[64];
    __shared__ int s_dj[64];

    int q    = blockIdx.y;
    int bz   = blockIdx.z;
    int b    = bz >> 1;
    int half = bz & 1;

    if (threadIdx.x < KKt) {
        int kk  = threadIdx.x;
        int t   = kk * Gg + q;
        int dc  = t / KKt;
        int kkp = t - dc * KKt;
        int r7  = kkp / 7;
        int di  = r7 - 3;
        int dj  = kkp - r7 * 7 - 3;
        s_off[kk] = dc * Ll + di * Ww + dj;
        s_di[kk]  = di;
        s_dj[kk]  = dj;
    }
    __syncthreads();

    int l = blockIdx.x * 256 + threadIdx.x;
    if (l >= Ll) return;
    int yp = l / Ww;
    int xp = l - yp * Ww;

    float acc[8];
#pragma unroll
    for (int i = 0; i < 8; i++) acc[i] = 0.f;

    const float* kb  = kgen + (size_t)b * M2 * Ll + (size_t)q * Ll + l;
    const float* xb  = x + (size_t)b * Cc * Ll + (size_t)(half * 8 * Gg) * Ll + l;

    bool interior = (yp >= 3) & (yp <= 52) & (xp >= 3) & (xp <= 52);

    if (interior) {
#pragma unroll 7
        for (int kk = 0; kk < KKt; kk++) {
            float kv = kb[(size_t)(kk * Gg) * Ll];
            const float* xpt = xb + s_off[kk];
#pragma unroll
            for (int cg = 0; cg < 8; cg++)
                acc[cg] = fmaf(kv, xpt[(size_t)cg * (Gg * Ll)], acc[cg]);
        }
    } else {
#pragma unroll 7
        for (int kk = 0; kk < KKt; kk++) {
            int yy = yp + s_di[kk];
            int xx = xp + s_dj[kk];
            if ((unsigned)yy < Hh && (unsigned)xx < Ww) {
                float kv = kb[(size_t)(kk * Gg) * Ll];
                const float* xpt = xb + s_off[kk];
#pragma unroll
                for (int cg = 0; cg < 8; cg++)
                    acc[cg] = fmaf(kv, xpt[(size_t)cg * (Gg * Ll)], acc[cg]);
            }
        }
    }

    float* ob = out + (size_t)b * Cc * Ll + (size_t)(half * 8 * Gg + q) * Ll + l;
#pragma unroll
    for (int cg = 0; cg < 8; cg++)
        ob[(size_t)(cg * Gg) * Ll] = acc[cg];
}

// ---------------------------------------------------------------------------
extern "C" void kernel_launch(void* const* d_in, const int* in_sizes, int n_in,
                              void* d_out, int out_size)
{
    const float* x     = (const float*)d_in[0];
    const float* w1    = (const float*)d_in[1];
    const float* b1    = (const float*)d_in[2];
    const float* gamma = (const float*)d_in[3];
    const float* beta  = (const float*)d_in[4];
    const float* w2    = (const float*)d_in[5];
    const float* b2    = (const float*)d_in[6];

    float* out  = (float*)d_out;
    float* kgen = out + OUT_OFF;

    float* t_ptr = nullptr;
    cudaGetSymbolAddress((void**)&t_ptr, g_t);

    // 1) conv1: t = w1 @ x + b1   (M=64, K=256)  -> TM=4 (64x64 tile)
    {
        dim3 grid(Ll / 64, 1, Bn);
        gemm_kernel<4, false><<<grid, 256>>>(w1, x, b1, t_ptr, CrD, Cc);
    }
    // 2) BN batch stats
    bn_stats_kernel<<<CrD, 256>>>(gamma, beta);

    // 3) conv2 + fused BN/ReLU: k = w2 @ relu(bn(t)) + b2  (M=784, K=64) -> TM=8
    {
        dim3 grid(Ll / 64, (M2 + 127) / 128, Bn);
        gemm_kernel<8, true><<<grid, 256>>>(w2, t_ptr, b2, kgen, M2, CrD);
    }
    // 4) involution contraction
    {
        dim3 grid((Ll + 255) / 256, Gg, Bn * 2);
        involution_kernel<<<grid, 256>>>(x, kgen, out);
    }
}

// round 4
// speedup vs baseline: 2.0411x; 1.0861x over previous
#include <cuda_runtime.h>
#include <math.h>

#define Bn   2
#define Cc   256
#define Hh   56
#define Ww   56
#define Ll   3136
#define CrD  64
#define Gg   16
#define KKt  49
#define M2   784
#define OUT_OFF (Bn*Cc*Ll)

__device__ float g_t[Bn*CrD*Ll];
__device__ float g_scale[CrD];
__device__ float g_shift[CrD];

// ---------------------------------------------------------------------------
// Tiled GEMM (unchanged from R2): C[b][m][n] = sum_k W[m][k]*f(A[b][k][n]) + bias
// ---------------------------------------------------------------------------
template<int TM, bool FUSE>
__global__ void gemm_kernel(const float* __restrict__ W,
                            const float* __restrict__ A,
                            const float* __restrict__ bias,
                            float* __restrict__ Cmat,
                            int M, int Kd)
{
    const int N  = Ll;
    const int BM = 16 * TM;
    __shared__ float Ws[16][16 * TM];
    __shared__ float As[16][64];

    int b   = blockIdx.z;
    int bm0 = blockIdx.y * BM;
    int bn0 = blockIdx.x * 64;
    int tid = threadIdx.x;
    int tx  = tid & 15;
    int ty  = tid >> 4;

    float acc[TM][4];
#pragma unroll
    for (int i = 0; i < TM; i++)
#pragma unroll
        for (int j = 0; j < 4; j++) acc[i][j] = 0.f;

    const float* Ab = A + (size_t)b * Kd * N;

    for (int k0 = 0; k0 < Kd; k0 += 16) {
#pragma unroll
        for (int i = 0; i < TM / 4; i++) {
            int idx = tid + i * 256;
            int m   = idx >> 2;
            int k4  = idx & 3;
            int gm  = bm0 + m;
            float4 v = make_float4(0.f, 0.f, 0.f, 0.f);
            if (gm < M)
                v = *(const float4*)&W[(size_t)gm * Kd + k0 + k4 * 4];
            Ws[k4 * 4 + 0][m] = v.x;
            Ws[k4 * 4 + 1][m] = v.y;
            Ws[k4 * 4 + 2][m] = v.z;
            Ws[k4 * 4 + 3][m] = v.w;
        }
        {
            int kk = tid >> 4;
            int n4 = tid & 15;
            float4 v = *(const float4*)&Ab[(size_t)(k0 + kk) * N + bn0 + n4 * 4];
            if (FUSE) {
                float sc = g_scale[k0 + kk], sh = g_shift[k0 + kk];
                v.x = fmaxf(fmaf(v.x, sc, sh), 0.f);
                v.y = fmaxf(fmaf(v.y, sc, sh), 0.f);
                v.z = fmaxf(fmaf(v.z, sc, sh), 0.f);
                v.w = fmaxf(fmaf(v.w, sc, sh), 0.f);
            }
            *(float4*)&As[kk][n4 * 4] = v;
        }
        __syncthreads();
#pragma unroll
        for (int kk = 0; kk < 16; kk++) {
            float4 a4 = *(const float4*)&As[kk][tx * 4];
            float wr[TM];
#pragma unroll
            for (int j = 0; j < TM / 4; j++) {
                float4 w4 = *(const float4*)&Ws[kk][ty * TM + j * 4];
                wr[j * 4 + 0] = w4.x; wr[j * 4 + 1] = w4.y;
                wr[j * 4 + 2] = w4.z; wr[j * 4 + 3] = w4.w;
            }
#pragma unroll
            for (int i = 0; i < TM; i++) {
                acc[i][0] = fmaf(wr[i], a4.x, acc[i][0]);
                acc[i][1] = fmaf(wr[i], a4.y, acc[i][1]);
                acc[i][2] = fmaf(wr[i], a4.z, acc[i][2]);
                acc[i][3] = fmaf(wr[i], a4.w, acc[i][3]);
            }
        }
        __syncthreads();
    }

#pragma unroll
    for (int i = 0; i < TM; i++) {
        int gm = bm0 + ty * TM + i;
        if (gm < M) {
            float bb = bias[gm];
            float4 v = make_float4(acc[i][0] + bb, acc[i][1] + bb,
                                   acc[i][2] + bb, acc[i][3] + bb);
            *(float4*)&Cmat[(size_t)b * M * N + (size_t)gm * N + bn0 + tx * 4] = v;
        }
    }
}

// ---------------------------------------------------------------------------
__global__ void bn_stats_kernel(const float* __restrict__ gamma,
                                const float* __restrict__ beta)
{
    int ch  = blockIdx.x;
    int tid = threadIdx.x;
    double ds = 0.0, ds2 = 0.0;
    for (int i = tid; i < Bn * Ll; i += 256) {
        int b = i / Ll;
        int l = i - b * Ll;
        float v = g_t[((size_t)b * CrD + ch) * Ll + l];
        ds  += v;
        ds2 += (double)v * v;
    }
    __shared__ double sh[256], sh2[256];
    sh[tid] = ds; sh2[tid] = ds2;
    __syncthreads();
    for (int o = 128; o > 0; o >>= 1) {
        if (tid < o) { sh[tid] += sh[tid + o]; sh2[tid] += sh2[tid + o]; }
        __syncthreads();
    }
    if (tid == 0) {
        double n    = (double)(Bn * Ll);
        double mean = sh[0] / n;
        double var  = sh2[0] / n - mean * mean;
        float rstd  = rsqrtf((float)var + 1e-5f);
        float sc    = gamma[ch] * rstd;
        g_scale[ch] = sc;
        g_shift[ch] = beta[ch] - (float)mean * sc;
    }
}

// ---------------------------------------------------------------------------
// Involution, smem-staged x tile.
// Block = (l-tile of 64, uq quarter of cg, b). 1024 threads = (v 0..15) x (lofs 0..63).
// Stage xs[64 ch][8 rows][64 cols] (zero-padded halo -> branch-free main loop).
// Each thread: fixed (v, l), 4 u accumulators; 49 taps:
//   1 LDG (kv, coalesced) + 1 LDS (per-v offset table, broadcast)
//   + 4 LDS (x, conflict-free) + 4 FFMA.
// xs addr = dc*512 + (y-y0+3+di)*64 + (xp+3+dj); OOB rows/cols are zero.
// ---------------------------------------------------------------------------
extern __shared__ float s_dyn[];

__global__ __launch_bounds__(1024, 1)
void involution_kernel(const float* __restrict__ x,
                       const float* __restrict__ kgen,
                       float* __restrict__ out)
{
    float* xs    = s_dyn;                 // 64*8*64 = 32768 floats (128 KB)
    int*   tab   = (int*)(s_dyn + 32768); // 16*49 offsets

    const int tid  = threadIdx.x;
    const int uq   = blockIdx.y;          // 0..3  (quarter of cg)
    const int b    = blockIdx.z;
    const int l0   = blockIdx.x * 64;
    const int y0   = l0 / Ww;             // tile spans rows y0, y0+1

    // --- offset table: tab[v*49+kkp] = dc*512 + di*64 + dj ---
    if (tid < 16 * KKt) {
        int v   = tid / KKt;
        int kkp = tid - v * KKt;
        int s   = kkp * Gg + v;
        int dc  = s / KKt;
        int tp  = s - dc * KKt;
        int r7  = tp / 7;
        int di  = r7 - 3;
        int dj  = tp - r7 * 7 - 3;
        tab[tid] = dc * 512 + di * 64 + dj;
    }

    // --- stage x tile: channels [uq*64, uq*64+64), rows y0-3..y0+4, cols -3..60 ---
    {
        const float* xb = x + ((size_t)b * Cc + uq * 64) * Ll;
#pragma unroll
        for (int i = 0; i < 32; i++) {
            int idx  = tid + i * 1024;
            int cl   = idx >> 9;          // 0..63
            int rem  = idx & 511;
            int yrel = rem >> 6;          // 0..7
            int j    = rem & 63;          // 0..63
            int yy   = y0 - 3 + yrel;
            int xcol = j - 3;
            float v = 0.f;
            if ((unsigned)yy < Hh && (unsigned)xcol < Ww)
                v = xb[(size_t)cl * Ll + yy * Ww + xcol];
            xs[idx] = v;
        }
    }
    __syncthreads();

    // --- main contraction ---
    const int v    = tid >> 6;            // 0..15
    const int lofs = tid & 63;
    const int l    = l0 + lofs;
    const int y    = l / Ww;
    const int xp   = l - y * Ww;
    const int thr_base = (y - y0 + 3) * 64 + (xp + 3);

    const float* kb = kgen + (size_t)b * M2 * Ll + (size_t)v * Ll + l;
    const int* tv = tab + v * KKt;

    float acc0 = 0.f, acc1 = 0.f, acc2 = 0.f, acc3 = 0.f;

#pragma unroll 7
    for (int kkp = 0; kkp < KKt; kkp++) {
        float kv = kb[(size_t)(kkp * Gg) * Ll];
        int   a  = tv[kkp] + thr_base;
        acc0 = fmaf(kv, xs[a        ], acc0);
        acc1 = fmaf(kv, xs[a + 8192 ], acc1);
        acc2 = fmaf(kv, xs[a + 16384], acc2);
        acc3 = fmaf(kv, xs[a + 24576], acc3);
    }

    // c_out = (uq*4+u)*16 + v
    float* ob = out + (size_t)b * Cc * Ll + (size_t)((uq * 4) * Gg + v) * Ll + l;
    ob[0 * Gg * Ll] = acc0;
    ob[1 * Gg * Ll] = acc1;
    ob[2 * Gg * Ll] = acc2;
    ob[3 * Gg * Ll] = acc3;
}

// ---------------------------------------------------------------------------
extern "C" void kernel_launch(void* const* d_in, const int* in_sizes, int n_in,
                              void* d_out, int out_size)
{
    const float* x     = (const float*)d_in[0];
    const float* w1    = (const float*)d_in[1];
    const float* b1    = (const float*)d_in[2];
    const float* gamma = (const float*)d_in[3];
    const float* beta  = (const float*)d_in[4];
    const float* w2    = (const float*)d_in[5];
    const float* b2    = (const float*)d_in[6];

    float* out  = (float*)d_out;
    float* kgen = out + OUT_OFF;

    float* t_ptr = nullptr;
    cudaGetSymbolAddress((void**)&t_ptr, g_t);

    // 1) conv1: t = w1 @ x + b1   (M=64, K=256)
    {
        dim3 grid(Ll / 64, 1, Bn);
        gemm_kernel<4, false><<<grid, 256>>>(w1, x, b1, t_ptr, CrD, Cc);
    }
    // 2) BN batch stats
    bn_stats_kernel<<<CrD, 256>>>(gamma, beta);

    // 3) conv2 + fused BN/ReLU (M=784, K=64)
    {
        dim3 grid(Ll / 64, (M2 + 127) / 128, Bn);
        gemm_kernel<8, true><<<grid, 256>>>(w2, t_ptr, b2, kgen, M2, CrD);
    }
    // 4) involution with smem-staged x
    {
        int smem_bytes = 32768 * 4 + 16 * KKt * 4;   // 131072 + 3136
        static int configured = 0;
        if (!configured) {
            cudaFuncSetAttribute(involution_kernel,
                                 cudaFuncAttributeMaxDynamicSharedMemorySize,
                                 smem_bytes);
            configured = 1;
        }
        dim3 grid(Ll / 64, 4, Bn);
        involution_kernel<<<grid, 1024, smem_bytes>>>(x, kgen, out);
    }
}